// round 9
// baseline (speedup 1.0000x reference)
#include <cuda_runtime.h>
#include <cuda_fp16.h>

// Problem constants (BOWRegressionMulti: T=200, B=1024, V=50000, L=512, PAD=1)
#define T_TOK 200
#define B_SZ  1024
#define V_SZ  50000
#define L_SZ  512
#define PAD_TOK 1
#define V_WORDS ((V_SZ + 31) / 32)

#define VTILES ((V_SZ + 63) / 64)          // 782
#define LTILES (L_SZ / 64)                 // 8
#define TR_BLOCKS (VTILES * LTILES)        // 6256 transpose blocks

// Scratch (static device globals — no allocs):
__device__ __half   g_Wt_h[(size_t)V_SZ * L_SZ];   // 51.2 MB transposed fp16 weights
__device__ unsigned g_toks[B_SZ][T_TOK];           // per-row deduped WORD offsets (v*256)
__device__ int      g_cnt[B_SZ];                   // per-row distinct-token counts

// ---------------------------------------------------------------------------
// K1 (fused): blocks [0, TR_BLOCKS) do the W[L,V] f32 -> Wt[V,L] f16 tiled
// transpose; blocks [TR_BLOCKS, TR_BLOCKS+B_SZ) do per-row token dedupe.
// ---------------------------------------------------------------------------
__global__ __launch_bounds__(256) void bow_prep_kernel(
    const float* __restrict__ W,          // [L, V] f32
    const int*   __restrict__ text)       // [T, B] int32
{
    __shared__ float tile[64][65];        // 16.64 KB (transpose) / bitmap (dedupe)
    const int bid = blockIdx.x;
    const int tid = threadIdx.x;

    if (bid < TR_BLOCKS) {
        // ---------------- transpose role ----------------
        const int v0 = (bid % VTILES) * 64;
        const int l0 = (bid / VTILES) * 64;

        {
            const int tx = tid & 15;
            const int ty = tid >> 4;
            const int v  = v0 + tx * 4;
            #pragma unroll
            for (int p = 0; p < 4; p++) {
                const int l = ty + p * 16;
                float4 val = make_float4(0.f, 0.f, 0.f, 0.f);
                if (v < V_SZ) {
                    val = __ldcs((const float4*)(W + (size_t)(l0 + l) * V_SZ + v));
                }
                tile[l][tx * 4 + 0] = val.x;
                tile[l][tx * 4 + 1] = val.y;
                tile[l][tx * 4 + 2] = val.z;
                tile[l][tx * 4 + 3] = val.w;
            }
        }
        __syncthreads();

        {
            const int wx = tid & 7;
            const int wy = tid >> 3;
            #pragma unroll
            for (int p = 0; p < 2; p++) {
                const int vr = wy + p * 32;
                const int v  = v0 + vr;
                if (v < V_SZ) {
                    const int lbase = wx * 8;
                    __half2 h[4];
                    #pragma unroll
                    for (int k = 0; k < 4; k++) {
                        h[k] = __floats2half2_rn(tile[lbase + 2 * k][vr],
                                                 tile[lbase + 2 * k + 1][vr]);
                    }
                    uint4 pkt;
                    pkt.x = *(unsigned int*)&h[0];
                    pkt.y = *(unsigned int*)&h[1];
                    pkt.z = *(unsigned int*)&h[2];
                    pkt.w = *(unsigned int*)&h[3];
                    *(uint4*)(g_Wt_h + (size_t)v * L_SZ + l0 + lbase) = pkt;
                }
            }
        }
    } else {
        // ---------------- dedupe role ----------------
        const int b = bid - TR_BLOCKS;
        unsigned int* bitmap = (unsigned int*)&tile[0][0];   // V_WORDS = 1563 words
        __shared__ int cnt;

        for (int i = tid; i < V_WORDS; i += 256) bitmap[i] = 0u;
        if (tid == 0) cnt = 0;
        __syncthreads();

        if (tid < T_TOK) {
            int v = text[(size_t)tid * B_SZ + b];
            if (v != PAD_TOK && (unsigned)v < (unsigned)V_SZ) {
                unsigned int bit = 1u << (v & 31);
                unsigned int old = atomicOr(&bitmap[v >> 5], bit);
                if (!(old & bit)) {
                    int idx = atomicAdd(&cnt, 1);
                    g_toks[b][idx] = (unsigned)v * (L_SZ / 2);  // WORD offset (uint32 units)
                }
            }
        }
        __syncthreads();
        if (tid == 0) g_cnt[b] = cnt;
    }
}

// ---------------------------------------------------------------------------
// K2: gather. One block = one batch row, 256 threads; thread t owns labels
// [2t, 2t+1]. Depth-2 fp16 pre-add tree (3 HADD2 per 4 tokens) before fp32
// accumulation: 2.75 issues/token vs 3.5 at depth-1. Error budget: adds a
// ~3.2e-4 component -> predicted total ~4.4e-4 (2.3x margin under 1e-3).
// __launch_bounds__(256, 8) pins regs <= 32 for full occupancy.
// ---------------------------------------------------------------------------
__global__ __launch_bounds__(256, 8) void bow_gather_kernel(
    const float* __restrict__ bias,       // [L]
    float* __restrict__ out)              // [B, L]
{
    __shared__ unsigned offs[T_TOK];
    const int b   = blockIdx.x;
    const int tid = threadIdx.x;

    const int n = g_cnt[b];
    if (tid < T_TOK) offs[tid] = g_toks[b][tid];
    __syncthreads();

    // Per-thread base: address = base + off*4 -> single IMAD.WIDE per load.
    const unsigned int* Wt_t = (const unsigned int*)g_Wt_h + tid;

    float2 a0 = ((const float2*)bias)[tid];
    float2 a1 = make_float2(0.f, 0.f);

    int j = 0;
    for (; j + 8 <= n; j += 8) {
        unsigned int u0 = Wt_t[offs[j + 0]];
        unsigned int u1 = Wt_t[offs[j + 1]];
        unsigned int u2 = Wt_t[offs[j + 2]];
        unsigned int u3 = Wt_t[offs[j + 3]];
        unsigned int u4 = Wt_t[offs[j + 4]];
        unsigned int u5 = Wt_t[offs[j + 5]];
        unsigned int u6 = Wt_t[offs[j + 6]];
        unsigned int u7 = Wt_t[offs[j + 7]];
        __half2 h01 = __hadd2(*(const __half2*)&u0, *(const __half2*)&u1);
        __half2 h23 = __hadd2(*(const __half2*)&u2, *(const __half2*)&u3);
        __half2 h45 = __hadd2(*(const __half2*)&u4, *(const __half2*)&u5);
        __half2 h67 = __hadd2(*(const __half2*)&u6, *(const __half2*)&u7);
        __half2 q0 = __hadd2(h01, h23);
        __half2 q1 = __hadd2(h45, h67);
        float2 f;
        f = __half22float2(q0); a0.x += f.x; a0.y += f.y;
        f = __half22float2(q1); a1.x += f.x; a1.y += f.y;
    }
    for (; j + 2 <= n; j += 2) {
        unsigned int u0 = Wt_t[offs[j + 0]];
        unsigned int u1 = Wt_t[offs[j + 1]];
        __half2 h = __hadd2(*(const __half2*)&u0, *(const __half2*)&u1);
        float2 f = __half22float2(h);
        a0.x += f.x; a0.y += f.y;
    }
    if (j < n) {
        unsigned int u = Wt_t[offs[j]];
        float2 f = __half22float2(*(const __half2*)&u);
        a1.x += f.x; a1.y += f.y;
    }

    float2 r;
    r.x = a0.x + a1.x;
    r.y = a0.y + a1.y;

    ((float2*)out)[(size_t)b * (L_SZ / 2) + tid] = r;
}

// ---------------------------------------------------------------------------
// Launch: fused prep (transpose + dedupe) then gather. Graph-capturable.
// Inputs: [0] text int32 [T,B], [1] W f32 [L,V], [2] b f32 [L].
// ---------------------------------------------------------------------------
extern "C" void kernel_launch(void* const* d_in, const int* in_sizes, int n_in,
                              void* d_out, int out_size) {
    const int*   text = (const int*)d_in[0];
    const float* W    = (const float*)d_in[1];
    const float* bias = (const float*)d_in[2];
    float*       out  = (float*)d_out;

    bow_prep_kernel<<<TR_BLOCKS + B_SZ, 256>>>(W, text);
    bow_gather_kernel<<<B_SZ, 256>>>(bias, out);
}

// round 10
// speedup vs baseline: 1.1049x; 1.1049x over previous
#include <cuda_runtime.h>
#include <cuda_fp16.h>

// Problem constants (BOWRegressionMulti: T=200, B=1024, V=50000, L=512, PAD=1)
#define T_TOK 200
#define B_SZ  1024
#define V_SZ  50000
#define L_SZ  512
#define PAD_TOK 1
#define V_WORDS ((V_SZ + 31) / 32)

#define VTILES ((V_SZ + 63) / 64)          // 782
#define LTILES (L_SZ / 64)                 // 8
#define TR_BLOCKS (VTILES * LTILES)        // 6256 transpose blocks

// Scratch (static device globals — no allocs):
__device__ __half   g_Wt_h[(size_t)V_SZ * L_SZ];   // 51.2 MB transposed fp16 weights
__device__ unsigned g_toks[B_SZ][T_TOK];           // per-row deduped uint2-offsets (v*128)
__device__ int      g_cnt[B_SZ];                   // per-row distinct-token counts

// ---------------------------------------------------------------------------
// K1 (fused): blocks [0, TR_BLOCKS) do the W[L,V] f32 -> Wt[V,L] f16 tiled
// transpose; blocks [TR_BLOCKS, TR_BLOCKS+B_SZ) do per-row token dedupe.
// ---------------------------------------------------------------------------
__global__ __launch_bounds__(256) void bow_prep_kernel(
    const float* __restrict__ W,          // [L, V] f32
    const int*   __restrict__ text)       // [T, B] int32
{
    __shared__ float tile[64][65];        // 16.64 KB (transpose) / bitmap (dedupe)
    const int bid = blockIdx.x;
    const int tid = threadIdx.x;

    if (bid < TR_BLOCKS) {
        // ---------------- transpose role ----------------
        const int v0 = (bid % VTILES) * 64;
        const int l0 = (bid / VTILES) * 64;

        {
            const int tx = tid & 15;
            const int ty = tid >> 4;
            const int v  = v0 + tx * 4;
            #pragma unroll
            for (int p = 0; p < 4; p++) {
                const int l = ty + p * 16;
                float4 val = make_float4(0.f, 0.f, 0.f, 0.f);
                if (v < V_SZ) {
                    val = __ldcs((const float4*)(W + (size_t)(l0 + l) * V_SZ + v));
                }
                tile[l][tx * 4 + 0] = val.x;
                tile[l][tx * 4 + 1] = val.y;
                tile[l][tx * 4 + 2] = val.z;
                tile[l][tx * 4 + 3] = val.w;
            }
        }
        __syncthreads();

        {
            const int wx = tid & 7;
            const int wy = tid >> 3;
            #pragma unroll
            for (int p = 0; p < 2; p++) {
                const int vr = wy + p * 32;
                const int v  = v0 + vr;
                if (v < V_SZ) {
                    const int lbase = wx * 8;
                    __half2 h[4];
                    #pragma unroll
                    for (int k = 0; k < 4; k++) {
                        h[k] = __floats2half2_rn(tile[lbase + 2 * k][vr],
                                                 tile[lbase + 2 * k + 1][vr]);
                    }
                    uint4 pkt;
                    pkt.x = *(unsigned int*)&h[0];
                    pkt.y = *(unsigned int*)&h[1];
                    pkt.z = *(unsigned int*)&h[2];
                    pkt.w = *(unsigned int*)&h[3];
                    *(uint4*)(g_Wt_h + (size_t)v * L_SZ + l0 + lbase) = pkt;
                }
            }
        }
    } else {
        // ---------------- dedupe role ----------------
        const int b = bid - TR_BLOCKS;
        unsigned int* bitmap = (unsigned int*)&tile[0][0];   // V_WORDS = 1563 words
        __shared__ int cnt;

        for (int i = tid; i < V_WORDS; i += 256) bitmap[i] = 0u;
        if (tid == 0) cnt = 0;
        __syncthreads();

        if (tid < T_TOK) {
            int v = text[(size_t)tid * B_SZ + b];
            if (v != PAD_TOK && (unsigned)v < (unsigned)V_SZ) {
                unsigned int bit = 1u << (v & 31);
                unsigned int old = atomicOr(&bitmap[v >> 5], bit);
                if (!(old & bit)) {
                    int idx = atomicAdd(&cnt, 1);
                    g_toks[b][idx] = (unsigned)v * (L_SZ / 4);  // uint2-offset units
                }
            }
        }
        __syncthreads();
        if (tid == 0) g_cnt[b] = cnt;
    }
}

// ---------------------------------------------------------------------------
// K2: gather, parity-split + 64-bit loads. 256 threads: g = tid>>7 = token
// parity, t = tid&127 owns labels [4t, 4t+4) via one uint2 (8B) load/token.
// Halves warp-LDG count and doubles bytes-in-flight at MLP=8 (gather is
// latency-bound per R9). Depth-2 fp16 pre-add tree, fp32 accumulation.
// Parity-1 partials staged in smem, combined with bias by parity-0 threads.
// ---------------------------------------------------------------------------
__global__ __launch_bounds__(256, 8) void bow_gather_kernel(
    const float* __restrict__ bias,       // [L]
    float* __restrict__ out)              // [B, L]
{
    __shared__ unsigned offs[T_TOK];
    __shared__ float4 part[128];          // parity-1 partials (2 KB)

    const int b   = blockIdx.x;
    const int tid = threadIdx.x;
    const int g   = tid >> 7;             // token parity
    const int t   = tid & 127;            // label group: labels [4t, 4t+4)

    const int n = g_cnt[b];
    if (tid < T_TOK) offs[tid] = g_toks[b][tid];
    __syncthreads();

    // Per-thread base: address = base + off*8 -> single IMAD.WIDE per load.
    const uint2* Wt_t = (const uint2*)g_Wt_h + t;

    const int m = (n - g + 1) >> 1;       // count of own-parity tokens

    float2 a0 = make_float2(0.f, 0.f);    // labels 4t,4t+1 (stream 0)
    float2 a1 = make_float2(0.f, 0.f);    // labels 4t+2,4t+3 (stream 0)
    float2 a2 = make_float2(0.f, 0.f);    // labels 4t,4t+1 (stream 1)
    float2 a3 = make_float2(0.f, 0.f);    // labels 4t+2,4t+3 (stream 1)

    int i = 0;
    for (; i + 8 <= m; i += 8) {
        uint2 u0 = Wt_t[offs[2 * (i + 0) + g]];
        uint2 u1 = Wt_t[offs[2 * (i + 1) + g]];
        uint2 u2 = Wt_t[offs[2 * (i + 2) + g]];
        uint2 u3 = Wt_t[offs[2 * (i + 3) + g]];
        uint2 u4 = Wt_t[offs[2 * (i + 4) + g]];
        uint2 u5 = Wt_t[offs[2 * (i + 5) + g]];
        uint2 u6 = Wt_t[offs[2 * (i + 6) + g]];
        uint2 u7 = Wt_t[offs[2 * (i + 7) + g]];
        // depth-1 pairs
        __half2 p0x = __hadd2(*(__half2*)&u0.x, *(__half2*)&u1.x);
        __half2 p0y = __hadd2(*(__half2*)&u0.y, *(__half2*)&u1.y);
        __half2 p1x = __hadd2(*(__half2*)&u2.x, *(__half2*)&u3.x);
        __half2 p1y = __hadd2(*(__half2*)&u2.y, *(__half2*)&u3.y);
        __half2 p2x = __hadd2(*(__half2*)&u4.x, *(__half2*)&u5.x);
        __half2 p2y = __hadd2(*(__half2*)&u4.y, *(__half2*)&u5.y);
        __half2 p3x = __hadd2(*(__half2*)&u6.x, *(__half2*)&u7.x);
        __half2 p3y = __hadd2(*(__half2*)&u6.y, *(__half2*)&u7.y);
        // depth-2 quads
        __half2 q0x = __hadd2(p0x, p1x);
        __half2 q0y = __hadd2(p0y, p1y);
        __half2 q1x = __hadd2(p2x, p3x);
        __half2 q1y = __hadd2(p2y, p3y);
        float2 f;
        f = __half22float2(q0x); a0.x += f.x; a0.y += f.y;
        f = __half22float2(q0y); a1.x += f.x; a1.y += f.y;
        f = __half22float2(q1x); a2.x += f.x; a2.y += f.y;
        f = __half22float2(q1y); a3.x += f.x; a3.y += f.y;
    }
    for (; i + 2 <= m; i += 2) {
        uint2 u0 = Wt_t[offs[2 * (i + 0) + g]];
        uint2 u1 = Wt_t[offs[2 * (i + 1) + g]];
        __half2 px = __hadd2(*(__half2*)&u0.x, *(__half2*)&u1.x);
        __half2 py = __hadd2(*(__half2*)&u0.y, *(__half2*)&u1.y);
        float2 f;
        f = __half22float2(px); a0.x += f.x; a0.y += f.y;
        f = __half22float2(py); a1.x += f.x; a1.y += f.y;
    }
    if (i < m) {
        uint2 u = Wt_t[offs[2 * i + g]];
        float2 f;
        f = __half22float2(*(__half2*)&u.x); a2.x += f.x; a2.y += f.y;
        f = __half22float2(*(__half2*)&u.y); a3.x += f.x; a3.y += f.y;
    }

    float4 s;
    s.x = a0.x + a2.x;
    s.y = a0.y + a2.y;
    s.z = a1.x + a3.x;
    s.w = a1.y + a3.y;

    if (g == 1) part[t] = s;
    __syncthreads();

    if (g == 0) {
        const float4 bs = ((const float4*)bias)[t];
        const float4 p  = part[t];
        float4 r;
        r.x = bs.x + s.x + p.x;
        r.y = bs.y + s.y + p.y;
        r.z = bs.z + s.z + p.z;
        r.w = bs.w + s.w + p.w;
        ((float4*)out)[(size_t)b * (L_SZ / 4) + t] = r;
    }
}

// ---------------------------------------------------------------------------
// Launch: fused prep (transpose + dedupe) then gather. Graph-capturable.
// Inputs: [0] text int32 [T,B], [1] W f32 [L,V], [2] b f32 [L].
// ---------------------------------------------------------------------------
extern "C" void kernel_launch(void* const* d_in, const int* in_sizes, int n_in,
                              void* d_out, int out_size) {
    const int*   text = (const int*)d_in[0];
    const float* W    = (const float*)d_in[1];
    const float* bias = (const float*)d_in[2];
    float*       out  = (float*)d_out;

    bow_prep_kernel<<<TR_BLOCKS + B_SZ, 256>>>(W, text);
    bow_gather_kernel<<<B_SZ, 256>>>(bias, out);
}